// round 3
// baseline (speedup 1.0000x reference)
#include <cuda_runtime.h>

// Problem constants
#define TT 512
#define BB 128
#define DD 256
#define HH 256

// =====================================================================
// Phase 1:  pre[t,b,j] = sum_d X[t,b,d] * Wi[j,d] + bh[j]
// GEMM  M = T*B = 65536, N = 256, K = 256, written into d_out in place.
// Tiling: BM=64, BN=256 (full N), BK=32; 256 threads; 8x8 microtile.
// =====================================================================
#define P1_BM 64
#define P1_BK 32
#define P1_BMP 65   // padded stride for As (conflict-free transpose stores)
#define P1_BNP 257  // padded stride for Bs (conflict-free stores + reads)

__global__ __launch_bounds__(256, 2)
void pre_gemm(const float* __restrict__ X, const float* __restrict__ Wi,
              const float* __restrict__ bh, float* __restrict__ out)
{
    __shared__ float As[P1_BK * P1_BMP];   // As[k][m]  (transposed A tile)
    __shared__ float Bs[P1_BK * P1_BNP];   // Bs[k][n]  (transposed Wi tile)

    const int tid = threadIdx.x;
    const int tx = tid & 31;   // 0..31  -> column group
    const int ty = tid >> 5;   // 0..7   -> row group
    const int row0 = blockIdx.x * P1_BM;

    float acc[8][8];
#pragma unroll
    for (int r = 0; r < 8; r++)
#pragma unroll
        for (int c = 0; c < 8; c++) acc[r][c] = 0.0f;

    for (int k0 = 0; k0 < DD; k0 += P1_BK) {
        // ---- load A tile: 64 rows x 32 k = 512 float4, 2 per thread ----
#pragma unroll
        for (int i = 0; i < 2; i++) {
            int lin = i * 256 + tid;
            int m  = lin >> 3;     // 0..63
            int kq = lin & 7;      // float4 index along k
            float4 v = *(const float4*)(X + (row0 + m) * DD + k0 + kq * 4);
            As[(kq * 4 + 0) * P1_BMP + m] = v.x;
            As[(kq * 4 + 1) * P1_BMP + m] = v.y;
            As[(kq * 4 + 2) * P1_BMP + m] = v.z;
            As[(kq * 4 + 3) * P1_BMP + m] = v.w;
        }
        // ---- load B tile: 256 n x 32 k = 2048 float4, 8 per thread ----
#pragma unroll
        for (int i = 0; i < 8; i++) {
            int lin = i * 256 + tid;
            int n  = lin >> 3;     // 0..255
            int kq = lin & 7;
            float4 v = *(const float4*)(Wi + n * DD + k0 + kq * 4);
            Bs[(kq * 4 + 0) * P1_BNP + n] = v.x;
            Bs[(kq * 4 + 1) * P1_BNP + n] = v.y;
            Bs[(kq * 4 + 2) * P1_BNP + n] = v.z;
            Bs[(kq * 4 + 3) * P1_BNP + n] = v.w;
        }
        __syncthreads();

#pragma unroll 8
        for (int k = 0; k < P1_BK; k++) {
            float a[8], b[8];
#pragma unroll
            for (int r = 0; r < 8; r++) a[r] = As[k * P1_BMP + ty * 8 + r];   // broadcast
#pragma unroll
            for (int c = 0; c < 8; c++) b[c] = Bs[k * P1_BNP + c * 32 + tx];  // conflict-free
#pragma unroll
            for (int r = 0; r < 8; r++)
#pragma unroll
                for (int c = 0; c < 8; c++) acc[r][c] += a[r] * b[c];
        }
        __syncthreads();
    }

    // ---- epilogue: add bias, store ----
    float bias[8];
#pragma unroll
    for (int c = 0; c < 8; c++) bias[c] = bh[c * 32 + tx];
#pragma unroll
    for (int r = 0; r < 8; r++) {
        float* orow = out + (row0 + ty * 8 + r) * HH;
#pragma unroll
        for (int c = 0; c < 8; c++)
            orow[c * 32 + tx] = acc[r][c] + bias[c];
    }
}

// =====================================================================
// Phase 2: sequential recurrence. One CTA per batch row b (128 CTAs),
// 256 threads; thread j computes h_new[j] each step.
//   Wh[j][0:160]   -> thread-j registers (40 float4 = 160 regs)
//   Wh[j][160:256] -> smem, interleaved layout so thread j does
//                     conflict-free LDS.128:
//                     Wh_s[c*1024 + j*4 + r] = Wh[j][160 + 4c + r], c=0..23
//   h              -> smem, double-buffered, broadcast LDS.128 reads
// pre[t] is read from d_out and overwritten with h_t in place.
// =====================================================================
#define P2_KREG 160                     // k-values held in registers
#define P2_KSM  (HH - P2_KREG)          // 96 k-values in smem
#define WHS_FLOATS ((P2_KSM / 4) * 1024)       // 24 groups x 256 j x 4
#define P2_SMEM_BYTES ((WHS_FLOATS + 2 * HH) * (int)sizeof(float))

__global__ __launch_bounds__(256, 1)
void rnn_seq(const float* __restrict__ Wh, const float* __restrict__ h0,
             float* __restrict__ out)
{
    extern __shared__ float sm[];
    float* Wh_s = sm;                 // interleaved [c:0..23][j:0..255][r:0..3]
    float* h_s  = sm + WHS_FLOATS;    // two buffers of 256 floats (16B aligned)

    const int j = threadIdx.x;
    const int b = blockIdx.x;

    // ---- register-resident weights: Wh[j][0:160] ----
    float4 wr[P2_KREG / 4];
#pragma unroll
    for (int i = 0; i < P2_KREG / 4; i++)
        wr[i] = *(const float4*)(Wh + j * HH + i * 4);

    // ---- smem-resident weights, interleaved for vectorized reads ----
    // Wh_s[(k>>2)*1024 + jj*4 + (k&3)] = Wh[jj][P2_KREG + k], k in 0..95
    for (int idx = j; idx < P2_KSM * 256; idx += 256) {
        int k  = idx % P2_KSM;
        int jj = idx / P2_KSM;
        Wh_s[(k >> 2) * 1024 + jj * 4 + (k & 3)] = Wh[jj * HH + P2_KREG + k];
    }
    h_s[j] = h0[b * HH + j];
    __syncthreads();

    const int base = b * HH + j;
    float pre = out[base];            // pre[0]

    for (int t = 0; t < TT; t++) {
        // prefetch next step's pre-activation early
        float pre_next = 0.0f;
        if (t + 1 < TT) pre_next = out[(t + 1) * (BB * HH) + base];

        const float* hc = h_s + (t & 1) * HH;
        const float4* wsm = (const float4*)(Wh_s) + j;   // + c*256 per iter

        float a0 = pre, a1 = 0.0f, a2 = 0.0f, a3 = 0.0f;
        // k = 0..159: weights from registers, h broadcast from smem
#pragma unroll
        for (int c = 0; c < P2_KREG / 4; c++) {
            float4 h4 = *(const float4*)(hc + c * 4);
            a0 += h4.x * wr[c].x;
            a1 += h4.y * wr[c].y;
            a2 += h4.z * wr[c].z;
            a3 += h4.w * wr[c].w;
        }
        // k = 160..255: weights from smem, conflict-free LDS.128
#pragma unroll
        for (int c = 0; c < P2_KSM / 4; c++) {
            float4 h4 = *(const float4*)(hc + P2_KREG + c * 4);
            float4 w4 = wsm[c * 256];
            a0 += h4.x * w4.x;
            a1 += h4.y * w4.y;
            a2 += h4.z * w4.z;
            a3 += h4.w * w4.w;
        }
        float z = (a0 + a1) + (a2 + a3);
        float hn = 1.0f / (1.0f + __expf(-z));

        out[t * (BB * HH) + base] = hn;          // result (overwrites consumed pre[t])
        h_s[((t + 1) & 1) * HH + j] = hn;        // next step's h
        __syncthreads();
        pre = pre_next;
    }
}

// =====================================================================
// Launch
// Inputs (metadata order): X [T,B,D], h [B,H], Wi [H,D], Wh [H,H], bh [H],
// many_to_many (==1 in this dataset -> output is hiddens [T,B,H]).
// =====================================================================
extern "C" void kernel_launch(void* const* d_in, const int* in_sizes, int n_in,
                              void* d_out, int out_size)
{
    const float* X  = (const float*)d_in[0];
    const float* h0 = (const float*)d_in[1];
    const float* Wi = (const float*)d_in[2];
    const float* Wh = (const float*)d_in[3];
    const float* bh = (const float*)d_in[4];
    float* out = (float*)d_out;

    // Phase 1: pre-activations into d_out
    pre_gemm<<<(TT * BB) / P1_BM, 256>>>(X, Wi, bh, out);

    // Phase 2: sequential recurrence (needs >48KB dynamic smem)
    cudaFuncSetAttribute(rnn_seq, cudaFuncAttributeMaxDynamicSharedMemorySize,
                         P2_SMEM_BYTES);
    rnn_seq<<<BB, 256, P2_SMEM_BYTES>>>(Wh, h0, out);
}